// round 13
// baseline (speedup 1.0000x reference)
#include <cuda_runtime.h>
#include <cuda_bf16.h>
#include <math.h>

// ConvLSTM, mma.sync m16n8k16 bf16 3-term split, step-split (A=conv_x on a
// low-priority stream, B=conv_h+LSTM chain), Round 13: small CTAs.
// CTA = 128 px (2 rows x 64) x 64 oc, 4 warps x 2 m-tiles, compact A smem
// layout [sp][k-half][pix][8] -> 55.8 KB/CTA -> 4 CTAs/SM (16 warps/SM).
// x: (8,16,64,64,64) f32, Wk: (256,128,3,3) f32
// out: [hid | cell], each 8*64*64*64 f32 (NCHW).

#define HW 64

__device__ __nv_bfloat16 g_xs[2][8][16][HW][HW][64];   // x channel-last hi/lo
__device__ __nv_bfloat16 g_hs[2][2][8][HW][HW][64];    // [parity][split] h hi/lo
__device__ __nv_bfloat16 g_wpk[4][8][19456];           // packed weights (hcg,kb)
__device__ __align__(16) __nv_bfloat16 g_zero16[8] = {};
__device__ float4 g_part[16][2097152];                 // per-step conv_x partial

// smem (bf16 elems):
//   input  [sp2][half2][pix 264][8] = 8448   (16896 B)
//   weights[sp2][ocl 64][152]       = 19456  (38912 B)
#define SIN_HALF_E  2112          // elems per (sp,half) plane (264 px x 8)
#define SIN_SP_E    4224          // elems per sp plane
#define SIN_ELEMS   8448
#define W_SP        (64 * 152)
#define SMEM_BYTES  ((8448 + 19456) * 2)   // 55808 B

// ---------------- prep kernels ----------------

__global__ void prep_x(const float* __restrict__ x)
{
    __shared__ float tile[64][65];
    int y  = blockIdx.x & 63;
    int bt = blockIdx.x >> 6;               // b*16 + t
    const float* src = x + (size_t)bt * 64 * 4096 + y * 64;
    for (int i = threadIdx.x; i < 64 * 64; i += 256) {
        int ic = i >> 6, xx = i & 63;
        tile[ic][xx] = src[ic * 4096 + xx];
    }
    __syncthreads();
    int b = bt >> 4, t = bt & 15;
    for (int i = threadIdx.x; i < 64 * 64; i += 256) {
        int xx = i >> 6, ic = i & 63;
        float v = tile[ic][xx];
        __nv_bfloat16 hi = __float2bfloat16(v);
        g_xs[0][b][t][y][xx][ic] = hi;
        g_xs[1][b][t][y][xx][ic] = __float2bfloat16(v - __bfloat162float(hi));
    }
}

__global__ void prep_wpk(const float* __restrict__ Wk)
{
    int i = blockIdx.x * blockDim.x + threadIdx.x;  // over 4*8*19456
    if (i >= 4 * 8 * 19456) return;
    int e   = i % 19456;
    int kb  = (i / 19456) & 7;
    int hcg = i / (19456 * 8);
    int sp  = e / 9728;
    int r   = e - sp * 9728;
    int ocl = r / 152;
    int kk  = r - ocl * 152;
    __nv_bfloat16 out = __float2bfloat16(0.f);
    if (kk < 144) {
        int tap = kk >> 4, ic = kk & 15;
        int oc  = (ocl >> 4) * 64 + hcg * 16 + (ocl & 15);
        int cin = kb * 16 + ic;
        float v = Wk[(size_t)(oc * 128 + cin) * 9 + tap];
        __nv_bfloat16 hi = __float2bfloat16(v);
        out = sp ? __float2bfloat16(v - __bfloat162float(hi)) : hi;
    }
    g_wpk[hcg][kb][e] = out;
}

// ---------------- helpers ----------------

__device__ __forceinline__ void ldsm4(unsigned &r0, unsigned &r1,
                                      unsigned &r2, unsigned &r3, unsigned a)
{
    asm volatile("ldmatrix.sync.aligned.m8n8.x4.shared.b16 {%0,%1,%2,%3}, [%4];"
                 : "=r"(r0), "=r"(r1), "=r"(r2), "=r"(r3) : "r"(a));
}

__device__ __forceinline__ void mma_bf16(float* c, const unsigned* a, const unsigned* b)
{
    asm volatile("mma.sync.aligned.m16n8k16.row.col.f32.bf16.bf16.f32 "
                 "{%0,%1,%2,%3},{%4,%5,%6,%7},{%8,%9},{%0,%1,%2,%3};"
                 : "+f"(c[0]), "+f"(c[1]), "+f"(c[2]), "+f"(c[3])
                 : "r"(a[0]), "r"(a[1]), "r"(a[2]), "r"(a[3]),
                   "r"(b[0]), "r"(b[1]));
}

__device__ __forceinline__ void cpasync16(unsigned dst, const void* src)
{
    asm volatile("cp.async.cg.shared.global [%0], [%1], 16;"
                 :: "r"(dst), "l"(src) : "memory");
}

// Shared 4-kb mainloop. HSRC=0: g_xs (uses t); HSRC=1: g_hs[t&1].
template <int HSRC>
__device__ __forceinline__ void conv_half(
    float acc[2][8][4], int t, int y0, int hcg, int b, int tid,
    const unsigned sIn, const unsigned sW,
    const unsigned* laneA, unsigned laneB)
{
    const int par_in = t & 1;
    const int wkbase = HSRC ? 4 : 0;

    for (int kb = 0; kb < 4; kb++) {
        if (kb > 0) __syncthreads();   // all warps done with smem

        // stage input: 2sp x 2half x 264 px (4 rows incl. halo x 66)
        for (int c = tid; c < 1056; c += 128) {
            int sp  = c / 528;
            int r   = c - sp * 528;
            int hf  = r / 264;
            int pix = r - hf * 264;
            int sy  = pix / 66, sx = pix - sy * 66;
            int gy  = y0 - 1 + sy, gx = sx - 1;
            const void* src = g_zero16;
            if ((unsigned)gy < 64u && (unsigned)gx < 64u)
                src = HSRC
                    ? (const void*)&g_hs[par_in][sp][b][gy][gx][kb * 16 + hf * 8]
                    : (const void*)&g_xs[sp][b][t][gy][gx][kb * 16 + hf * 8];
            unsigned dst = sIn + (unsigned)((sp * 2 + hf) * 264 + pix) * 16u;
            cpasync16(dst, src);
        }
        // stage weights: contiguous packed block (2432 x 16B)
        {
            const char* wsrc = (const char*)g_wpk[hcg][wkbase + kb];
            for (int i = tid; i < 2432; i += 128)
                cpasync16(sW + (unsigned)i * 16u, wsrc + (size_t)i * 16);
        }
        asm volatile("cp.async.commit_group;" ::: "memory");
        asm volatile("cp.async.wait_group 0;" ::: "memory");
        __syncthreads();

#pragma unroll 1
        for (int tap = 0; tap < 9; tap++) {
            const int dyp = tap / 3, dxp = tap - dyp * 3;
            const unsigned aoff = (unsigned)(dyp * 66 + dxp) * 16u;
            const unsigned woff = (unsigned)(tap * 16) * 2u;

            unsigned a[2][2][4];   // [mt][sp][frag]
#pragma unroll
            for (int mt = 0; mt < 2; mt++) {
                ldsm4(a[mt][0][0], a[mt][0][1], a[mt][0][2], a[mt][0][3],
                      sIn + aoff + laneA[mt]);
                ldsm4(a[mt][1][0], a[mt][1][1], a[mt][1][2], a[mt][1][3],
                      sIn + (unsigned)(SIN_SP_E * 2) + aoff + laneA[mt]);
            }

            unsigned bf[8][2];
            {   // phase 1: B = w_hi  (Ah*Bh, Al*Bh)
                unsigned base = sW + woff + laneB;
#pragma unroll
                for (int j = 0; j < 4; j++)
                    ldsm4(bf[2 * j][0], bf[2 * j][1],
                          bf[2 * j + 1][0], bf[2 * j + 1][1],
                          base + (unsigned)(16 * j * 152) * 2u);
#pragma unroll
                for (int nf = 0; nf < 8; nf++)
#pragma unroll
                    for (int mt = 0; mt < 2; mt++) {
                        mma_bf16(acc[mt][nf], a[mt][0], bf[nf]);
                        mma_bf16(acc[mt][nf], a[mt][1], bf[nf]);
                    }
            }
            {   // phase 2: B = w_lo  (Ah*Bl)
                unsigned base = sW + (unsigned)(W_SP * 2) + woff + laneB;
#pragma unroll
                for (int j = 0; j < 4; j++)
                    ldsm4(bf[2 * j][0], bf[2 * j][1],
                          bf[2 * j + 1][0], bf[2 * j + 1][1],
                          base + (unsigned)(16 * j * 152) * 2u);
#pragma unroll
                for (int nf = 0; nf < 8; nf++)
#pragma unroll
                    for (int mt = 0; mt < 2; mt++)
                        mma_bf16(acc[mt][nf], a[mt][0], bf[nf]);
            }
        }
    }
}

__device__ __forceinline__ void lane_setup(int w, int lane,
                                           unsigned* laneA, unsigned& laneB)
{
    const int t4 = lane >> 3, r8 = lane & 7;
    const int prA = ((t4 & 1) << 3) + r8;
    const int k8A = t4 >> 1;
#pragma unroll
    for (int mt = 0; mt < 2; mt++) {
        const int p0  = w * 32 + mt * 16 + prA;   // 0..127
        const int pyA = p0 >> 6;                  // local row 0/1
        const int pxA = p0 & 63;
        laneA[mt] = (unsigned)(k8A * SIN_HALF_E + (pyA * 66 + pxA) * 8) * 2u;
    }
    const int hi8 = (t4 >= 2) ? 8 : 0;
    laneB = (unsigned)((hi8 + r8) * 152 + 8 * (t4 & 1)) * 2u;
}

// ---------------- kernel A: conv_x half -> partial ----------------

__global__ __launch_bounds__(128, 4)
void conv_x_half(int t)
{
    extern __shared__ __nv_bfloat16 smem[];
    const unsigned sIn = (unsigned)__cvta_generic_to_shared(smem);
    const unsigned sW  = sIn + SIN_ELEMS * 2;

    const int tid  = threadIdx.x;
    const int w    = tid >> 5;
    const int lane = tid & 31;
    const int y0   = blockIdx.x * 2;
    const int hcg  = blockIdx.y;
    const int b    = blockIdx.z;

    unsigned laneA[2], laneB;
    lane_setup(w, lane, laneA, laneB);

    float acc[2][8][4];
#pragma unroll
    for (int m = 0; m < 2; m++)
#pragma unroll
        for (int i = 0; i < 8; i++)
#pragma unroll
            for (int j = 0; j < 4; j++) acc[m][i][j] = 0.f;

    conv_half<0>(acc, t, y0, hcg, b, tid, sIn, sW, laneA, laneB);

    const int slot = ((int)blockIdx.x * 4 + hcg) * 8 + b;   // 0..1023
    float4* dst = g_part[t];
#pragma unroll
    for (int m = 0; m < 2; m++)
#pragma unroll
        for (int i = 0; i < 8; i++) {
            float4 v;
            v.x = acc[m][i][0]; v.y = acc[m][i][1];
            v.z = acc[m][i][2]; v.w = acc[m][i][3];
            dst[((size_t)slot * 16 + (m * 8 + i)) * 128 + tid] = v;
        }
}

// ---------------- kernel B: conv_h half + LSTM epilogue ----------------

__global__ __launch_bounds__(128, 4)
void conv_h_half(float* __restrict__ hid_out, float* __restrict__ cell_io,
                 int t, int last)
{
    extern __shared__ __nv_bfloat16 smem[];
    const unsigned sIn = (unsigned)__cvta_generic_to_shared(smem);
    const unsigned sW  = sIn + SIN_ELEMS * 2;

    const int tid  = threadIdx.x;
    const int w    = tid >> 5;
    const int lane = tid & 31;
    const int y0   = blockIdx.x * 2;
    const int hcg  = blockIdx.y;
    const int b    = blockIdx.z;
    const int par_out = (t + 1) & 1;

    unsigned laneA[2], laneB;
    lane_setup(w, lane, laneA, laneB);

    const int slot = ((int)blockIdx.x * 4 + hcg) * 8 + b;
    const float4* srcp = g_part[t];
    float acc[2][8][4];
#pragma unroll
    for (int m = 0; m < 2; m++)
#pragma unroll
        for (int i = 0; i < 8; i++) {
            float4 v = srcp[((size_t)slot * 16 + (m * 8 + i)) * 128 + tid];
            acc[m][i][0] = v.x; acc[m][i][1] = v.y;
            acc[m][i][2] = v.z; acc[m][i][3] = v.w;
        }

    if (t > 0)
        conv_half<1>(acc, t, y0, hcg, b, tid, sIn, sW, laneA, laneB);

    // ---- fused LSTM epilogue ----
    const int c0    = (lane & 3) * 2;
    const int rbase = lane >> 2;
#pragma unroll
    for (int mt = 0; mt < 2; mt++) {
#pragma unroll
        for (int rr = 0; rr < 2; rr++) {
            const int pe = w * 32 + mt * 16 + rbase + 8 * rr;
            const int y  = y0 + (pe >> 6);
            const int x  = pe & 63;
#pragma unroll
            for (int q = 0; q < 4; q++) {
                const int hcl  = c0 + (q & 1) + ((q >> 1) << 3);
                const int off2 = (hcl >= 8) ? 1 : 0;
                const int cidx = (hcl & 7) - c0 + rr * 2;
                float vi = acc[mt][0 + off2][cidx];
                float vf = acc[mt][2 + off2][cidx];
                float vo = acc[mt][4 + off2][cidx];
                float vg = acc[mt][6 + off2][cidx];
                float iv = 1.f / (1.f + __expf(-vi));
                float fv = 1.f / (1.f + __expf(-vf));
                float ov = 1.f / (1.f + __expf(-vo));
                float gv = tanhf(vg);
                const int hc = hcg * 16 + hcl;
                const size_t addr = (((size_t)b * 64 + hc) * 64 + y) * 64 + x;
                float cold = (t == 0) ? 0.f : cell_io[addr];
                float cnew = fv * cold + iv * gv;
                cell_io[addr] = cnew;
                float hval = ov * tanhf(cnew);
                if (last) {
                    hid_out[addr] = hval;
                } else {
                    __nv_bfloat16 hh = __float2bfloat16(hval);
                    g_hs[par_out][0][b][y][x][hc] = hh;
                    g_hs[par_out][1][b][y][x][hc] =
                        __float2bfloat16(hval - __bfloat162float(hh));
                }
            }
        }
    }
}

// ---------------- host: streams/events (created pre-main) ----------------

static cudaStream_t g_s1 = 0;
static cudaEvent_t  g_fork = 0, g_ea[16];
static bool g_streams_ok = false;

struct StreamInit {
    StreamInit() {
        int lo = 0, hi = 0;
        if (cudaDeviceGetStreamPriorityRange(&lo, &hi) != cudaSuccess) return;
        if (cudaStreamCreateWithPriority(&g_s1, cudaStreamNonBlocking, lo)
            != cudaSuccess) return;                 // lo = least priority
        if (cudaEventCreateWithFlags(&g_fork, cudaEventDisableTiming)
            != cudaSuccess) return;
        for (int i = 0; i < 16; i++)
            if (cudaEventCreateWithFlags(&g_ea[i], cudaEventDisableTiming)
                != cudaSuccess) return;
        g_streams_ok = true;
    }
};
static StreamInit g_stream_init;

extern "C" void kernel_launch(void* const* d_in, const int* in_sizes, int n_in,
                              void* d_out, int out_size)
{
    const float* x  = (const float*)d_in[0];
    const float* Wk = (const float*)d_in[1];
    float* out  = (float*)d_out;
    float* hid  = out;
    float* cell = out + out_size / 2;

    static bool attr_done = false;
    if (!attr_done) {
        cudaFuncSetAttribute(conv_x_half,
                             cudaFuncAttributeMaxDynamicSharedMemorySize, SMEM_BYTES);
        cudaFuncSetAttribute(conv_h_half,
                             cudaFuncAttributeMaxDynamicSharedMemorySize, SMEM_BYTES);
        attr_done = true;
    }

    prep_wpk<<<(4 * 8 * 19456 + 255) / 256, 256>>>(Wk);
    prep_x<<<8 * 16 * 64, 256>>>(x);

    dim3 grid(32, 4, 8), blk(128);

    if (g_streams_ok) {
        cudaEventRecord(g_fork, 0);
        cudaStreamWaitEvent(g_s1, g_fork, 0);
        for (int t = 0; t < 16; t++) {
            conv_x_half<<<grid, blk, SMEM_BYTES, g_s1>>>(t);
            cudaEventRecord(g_ea[t], g_s1);
        }
        for (int t = 0; t < 16; t++) {
            cudaStreamWaitEvent(0, g_ea[t], 0);
            conv_h_half<<<grid, blk, SMEM_BYTES>>>(hid, cell, t, t == 15 ? 1 : 0);
        }
    } else {
        for (int t = 0; t < 16; t++) {
            conv_x_half<<<grid, blk, SMEM_BYTES>>>(t);
            conv_h_half<<<grid, blk, SMEM_BYTES>>>(hid, cell, t, t == 15 ? 1 : 0);
        }
    }
}

// round 14
// speedup vs baseline: 1.4626x; 1.4626x over previous
#include <cuda_runtime.h>
#include <cuda_fp16.h>
#include <math.h>

// ConvLSTM, mma.sync m16n8k16 fp16 2-TERM split, step-split A/B kernels.
// W = Bh + Bl (fp16 hi/lo); input only Ah = fp16(A).
// D = Ah*Bh + Ah*Bl = Ah*W  (drops Sum Al*W, rel err ~2.8e-4 < 1e-3).
// 33% less tensor work than the bf16 3-term split; input staging halves.
// A(t)=conv_x on low-priority stream -> partial; B(t)=conv_h+LSTM chain.
// CTA = 256 px (4 rows x 64) x 64 oc, 8 warps, 2 m-tiles/warp, 2 CTAs/SM.
// x: (8,16,64,64,64) f32, Wk: (256,128,3,3) f32
// out: [hid | cell], each 8*64*64*64 f32 (NCHW).

#define HW 64

__device__ __half g_xs[8][16][HW][HW][64];     // x channel-last fp16
__device__ __half g_hs[2][8][HW][HW][64];      // [parity] h fp16
__device__ __half g_wpk[4][8][19456];          // packed weights (hcg,kb): [sp][ocl][152]
__device__ __align__(16) __half g_zero16[8] = {};
__device__ float4 g_part[16][2097152];         // per-step conv_x partial

// smem (fp16 elems): in buf = [k8half2][pix 396][8] = 6336 (x2 buffers)
//                    w  buf = [sp2][ocl 64][152]    = 19456
#define SIN_HALF_E  3168
#define SIN_BUF_E   6336
#define W_SP        9728            // elems per weight sp plane
#define SMEM_BYTES  ((2 * 6336 + 19456) * 2)   // 64256 B -> 2 CTAs/SM

// ---------------- prep kernels ----------------

__global__ void prep_x(const float* __restrict__ x)
{
    __shared__ float tile[64][65];
    int y  = blockIdx.x & 63;
    int bt = blockIdx.x >> 6;               // b*16 + t
    const float* src = x + (size_t)bt * 64 * 4096 + y * 64;
    for (int i = threadIdx.x; i < 64 * 64; i += 256) {
        int ic = i >> 6, xx = i & 63;
        tile[ic][xx] = src[ic * 4096 + xx];
    }
    __syncthreads();
    int b = bt >> 4, t = bt & 15;
    for (int i = threadIdx.x; i < 64 * 64; i += 256) {
        int xx = i >> 6, ic = i & 63;
        g_xs[b][t][y][xx][ic] = __float2half(tile[ic][xx]);
    }
}

// Pack weights for (hcg,kb): [sp][ocl 64][k 152], k = tap*16+ic (144 valid).
// sp0 = fp16 hi, sp1 = fp16 residual.
__global__ void prep_wpk(const float* __restrict__ Wk)
{
    int i = blockIdx.x * blockDim.x + threadIdx.x;  // over 4*8*19456
    if (i >= 4 * 8 * 19456) return;
    int e   = i % 19456;
    int kb  = (i / 19456) & 7;
    int hcg = i / (19456 * 8);
    int sp  = e / 9728;
    int r   = e - sp * 9728;
    int ocl = r / 152;
    int kk  = r - ocl * 152;
    __half out = __float2half(0.f);
    if (kk < 144) {
        int tap = kk >> 4, ic = kk & 15;
        int oc  = (ocl >> 4) * 64 + hcg * 16 + (ocl & 15);
        int cin = kb * 16 + ic;
        float v = Wk[(size_t)(oc * 128 + cin) * 9 + tap];
        __half hi = __float2half(v);
        out = sp ? __float2half(v - __half2float(hi)) : hi;
    }
    g_wpk[hcg][kb][e] = out;
}

// ---------------- helpers ----------------

__device__ __forceinline__ void ldsm4(unsigned &r0, unsigned &r1,
                                      unsigned &r2, unsigned &r3, unsigned a)
{
    asm volatile("ldmatrix.sync.aligned.m8n8.x4.shared.b16 {%0,%1,%2,%3}, [%4];"
                 : "=r"(r0), "=r"(r1), "=r"(r2), "=r"(r3) : "r"(a));
}

__device__ __forceinline__ void mma_f16(float* c, const unsigned* a, const unsigned* b)
{
    asm volatile("mma.sync.aligned.m16n8k16.row.col.f32.f16.f16.f32 "
                 "{%0,%1,%2,%3},{%4,%5,%6,%7},{%8,%9},{%0,%1,%2,%3};"
                 : "+f"(c[0]), "+f"(c[1]), "+f"(c[2]), "+f"(c[3])
                 : "r"(a[0]), "r"(a[1]), "r"(a[2]), "r"(a[3]),
                   "r"(b[0]), "r"(b[1]));
}

__device__ __forceinline__ void cpasync16(unsigned dst, const void* src)
{
    asm volatile("cp.async.cg.shared.global [%0], [%1], 16;"
                 :: "r"(dst), "l"(src) : "memory");
}

// Shared 4-kb mainloop. HSRC=0: g_xs (uses t); HSRC=1: g_hs[t&1].
template <int HSRC>
__device__ __forceinline__ void conv_half(
    float acc[2][8][4], int t, int y0, int hcg, int b, int tid,
    const unsigned sIn0, const unsigned sIn1, const unsigned sW,
    const unsigned* laneA, unsigned laneB)
{
    const int par_in = t & 1;
    const int wkbase = HSRC ? 4 : 0;

    auto load_input = [&](int kb, unsigned sIn) {
        for (int c = tid; c < 792; c += 256) {
            int hf  = c / 396;
            int pix = c - hf * 396;
            int sy  = pix / 66, sx = pix - sy * 66;
            int gy  = y0 - 1 + sy, gx = sx - 1;
            const void* src = g_zero16;
            if ((unsigned)gy < 64u && (unsigned)gx < 64u)
                src = HSRC
                    ? (const void*)&g_hs[par_in][b][gy][gx][kb * 16 + hf * 8]
                    : (const void*)&g_xs[b][t][gy][gx][kb * 16 + hf * 8];
            unsigned dst = sIn + (unsigned)(hf * 396 + pix) * 16u;
            cpasync16(dst, src);
        }
    };

    load_input(0, sIn0);
    asm volatile("cp.async.commit_group;" ::: "memory");

    for (int kb = 0; kb < 4; kb++) {
        if (kb > 0) __syncthreads();

        {   // stage weights(kb): contiguous packed block (2432 x 16B)
            const char* wsrc = (const char*)g_wpk[hcg][wkbase + kb];
            for (int i = tid; i < 2432; i += 256)
                cpasync16(sW + (unsigned)i * 16u, wsrc + (size_t)i * 16);
        }
        asm volatile("cp.async.commit_group;" ::: "memory");

        if (kb + 1 < 4) {
            load_input(kb + 1, (kb + 1) & 1 ? sIn1 : sIn0);
            asm volatile("cp.async.commit_group;" ::: "memory");
            asm volatile("cp.async.wait_group 1;" ::: "memory");
        } else {
            asm volatile("cp.async.wait_group 0;" ::: "memory");
        }
        __syncthreads();

        const unsigned sIn = (kb & 1) ? sIn1 : sIn0;

#pragma unroll 1
        for (int tap = 0; tap < 9; tap++) {
            const int dyp = tap / 3, dxp = tap - dyp * 3;
            const unsigned aoff = (unsigned)(dyp * 66 + dxp) * 16u;
            const unsigned woff = (unsigned)(tap * 16) * 2u;

            unsigned a[2][4];   // [mt][frag]  (single split plane)
#pragma unroll
            for (int mt = 0; mt < 2; mt++)
                ldsm4(a[mt][0], a[mt][1], a[mt][2], a[mt][3],
                      sIn + aoff + laneA[mt]);

            unsigned bf[8][2];
            {   // phase 1: B = w_hi  (Ah*Bh)
                unsigned base = sW + woff + laneB;
#pragma unroll
                for (int j = 0; j < 4; j++)
                    ldsm4(bf[2 * j][0], bf[2 * j][1],
                          bf[2 * j + 1][0], bf[2 * j + 1][1],
                          base + (unsigned)(16 * j * 152) * 2u);
#pragma unroll
                for (int nf = 0; nf < 8; nf++)
#pragma unroll
                    for (int mt = 0; mt < 2; mt++)
                        mma_f16(acc[mt][nf], a[mt], bf[nf]);
            }
            {   // phase 2: B = w_lo  (Ah*Bl)
                unsigned base = sW + (unsigned)(W_SP * 2) + woff + laneB;
#pragma unroll
                for (int j = 0; j < 4; j++)
                    ldsm4(bf[2 * j][0], bf[2 * j][1],
                          bf[2 * j + 1][0], bf[2 * j + 1][1],
                          base + (unsigned)(16 * j * 152) * 2u);
#pragma unroll
                for (int nf = 0; nf < 8; nf++)
#pragma unroll
                    for (int mt = 0; mt < 2; mt++)
                        mma_f16(acc[mt][nf], a[mt], bf[nf]);
            }
        }
    }
}

__device__ __forceinline__ void lane_setup(int w, int lane,
                                           unsigned* laneA, unsigned& laneB)
{
    const int t4 = lane >> 3, r8 = lane & 7;
    const int prA = ((t4 & 1) << 3) + r8;
    const int k8A = t4 >> 1;
#pragma unroll
    for (int mt = 0; mt < 2; mt++) {
        const int p0  = w * 32 + mt * 16 + prA;   // 0..255
        const int pyA = p0 >> 6;                  // local row 0..3
        const int pxA = p0 & 63;
        laneA[mt] = (unsigned)(k8A * SIN_HALF_E + (pyA * 66 + pxA) * 8) * 2u;
    }
    const int hi8 = (t4 >= 2) ? 8 : 0;
    laneB = (unsigned)((hi8 + r8) * 152 + 8 * (t4 & 1)) * 2u;
}

// ---------------- kernel A: conv_x half -> partial ----------------

__global__ __launch_bounds__(256, 2)
void conv_x_half(int t)
{
    extern __shared__ __half smem[];
    const unsigned sIn0 = (unsigned)__cvta_generic_to_shared(smem);
    const unsigned sIn1 = sIn0 + SIN_BUF_E * 2;
    const unsigned sW   = sIn0 + 2 * SIN_BUF_E * 2;

    const int tid  = threadIdx.x;
    const int w    = tid >> 5;
    const int lane = tid & 31;
    const int y0   = blockIdx.x * 4;
    const int hcg  = blockIdx.y;
    const int b    = blockIdx.z;

    unsigned laneA[2], laneB;
    lane_setup(w, lane, laneA, laneB);

    float acc[2][8][4];
#pragma unroll
    for (int m = 0; m < 2; m++)
#pragma unroll
        for (int i = 0; i < 8; i++)
#pragma unroll
            for (int j = 0; j < 4; j++) acc[m][i][j] = 0.f;

    conv_half<0>(acc, t, y0, hcg, b, tid, sIn0, sIn1, sW, laneA, laneB);

    const int slot = ((int)blockIdx.x * 4 + hcg) * 8 + b;   // 0..511
    float4* dst = g_part[t];
#pragma unroll
    for (int m = 0; m < 2; m++)
#pragma unroll
        for (int i = 0; i < 8; i++) {
            float4 v;
            v.x = acc[m][i][0]; v.y = acc[m][i][1];
            v.z = acc[m][i][2]; v.w = acc[m][i][3];
            dst[((size_t)slot * 16 + (m * 8 + i)) * 256 + tid] = v;
        }
}

// ---------------- kernel B: conv_h half + LSTM epilogue ----------------

__global__ __launch_bounds__(256, 2)
void conv_h_half(float* __restrict__ hid_out, float* __restrict__ cell_io,
                 int t, int last)
{
    extern __shared__ __half smem[];
    const unsigned sIn0 = (unsigned)__cvta_generic_to_shared(smem);
    const unsigned sIn1 = sIn0 + SIN_BUF_E * 2;
    const unsigned sW   = sIn0 + 2 * SIN_BUF_E * 2;

    const int tid  = threadIdx.x;
    const int w    = tid >> 5;
    const int lane = tid & 31;
    const int y0   = blockIdx.x * 4;
    const int hcg  = blockIdx.y;
    const int b    = blockIdx.z;
    const int par_out = (t + 1) & 1;

    unsigned laneA[2], laneB;
    lane_setup(w, lane, laneA, laneB);

    const int slot = ((int)blockIdx.x * 4 + hcg) * 8 + b;
    const float4* srcp = g_part[t];
    float acc[2][8][4];
#pragma unroll
    for (int m = 0; m < 2; m++)
#pragma unroll
        for (int i = 0; i < 8; i++) {
            float4 v = srcp[((size_t)slot * 16 + (m * 8 + i)) * 256 + tid];
            acc[m][i][0] = v.x; acc[m][i][1] = v.y;
            acc[m][i][2] = v.z; acc[m][i][3] = v.w;
        }

    if (t > 0)
        conv_half<1>(acc, t, y0, hcg, b, tid, sIn0, sIn1, sW, laneA, laneB);

    // ---- fused LSTM epilogue ----
    const int c0    = (lane & 3) * 2;
    const int rbase = lane >> 2;
#pragma unroll
    for (int mt = 0; mt < 2; mt++) {
#pragma unroll
        for (int rr = 0; rr < 2; rr++) {
            const int pe = w * 32 + mt * 16 + rbase + 8 * rr;
            const int y  = y0 + (pe >> 6);
            const int x  = pe & 63;
#pragma unroll
            for (int q = 0; q < 4; q++) {
                const int hcl  = c0 + (q & 1) + ((q >> 1) << 3);
                const int off2 = (hcl >= 8) ? 1 : 0;
                const int cidx = (hcl & 7) - c0 + rr * 2;
                float vi = acc[mt][0 + off2][cidx];
                float vf = acc[mt][2 + off2][cidx];
                float vo = acc[mt][4 + off2][cidx];
                float vg = acc[mt][6 + off2][cidx];
                float iv = 1.f / (1.f + __expf(-vi));
                float fv = 1.f / (1.f + __expf(-vf));
                float ov = 1.f / (1.f + __expf(-vo));
                float gv = tanhf(vg);
                const int hc = hcg * 16 + hcl;
                const size_t addr = (((size_t)b * 64 + hc) * 64 + y) * 64 + x;
                float cold = (t == 0) ? 0.f : cell_io[addr];
                float cnew = fv * cold + iv * gv;
                cell_io[addr] = cnew;
                float hval = ov * tanhf(cnew);
                if (last)
                    hid_out[addr] = hval;
                else
                    g_hs[par_out][b][y][x][hc] = __float2half(hval);
            }
        }
    }
}

// ---------------- host: streams/events (created pre-main) ----------------

static cudaStream_t g_s1 = 0;
static cudaEvent_t  g_fork = 0, g_ea[16];
static bool g_streams_ok = false;

struct StreamInit {
    StreamInit() {
        int lo = 0, hi = 0;
        if (cudaDeviceGetStreamPriorityRange(&lo, &hi) != cudaSuccess) return;
        if (cudaStreamCreateWithPriority(&g_s1, cudaStreamNonBlocking, lo)
            != cudaSuccess) return;
        if (cudaEventCreateWithFlags(&g_fork, cudaEventDisableTiming)
            != cudaSuccess) return;
        for (int i = 0; i < 16; i++)
            if (cudaEventCreateWithFlags(&g_ea[i], cudaEventDisableTiming)
                != cudaSuccess) return;
        g_streams_ok = true;
    }
};
static StreamInit g_stream_init;

extern "C" void kernel_launch(void* const* d_in, const int* in_sizes, int n_in,
                              void* d_out, int out_size)
{
    const float* x  = (const float*)d_in[0];
    const float* Wk = (const float*)d_in[1];
    float* out  = (float*)d_out;
    float* hid  = out;
    float* cell = out + out_size / 2;

    static bool attr_done = false;
    if (!attr_done) {
        cudaFuncSetAttribute(conv_x_half,
                             cudaFuncAttributeMaxDynamicSharedMemorySize, SMEM_BYTES);
        cudaFuncSetAttribute(conv_h_half,
                             cudaFuncAttributeMaxDynamicSharedMemorySize, SMEM_BYTES);
        attr_done = true;
    }

    prep_wpk<<<(4 * 8 * 19456 + 255) / 256, 256>>>(Wk);
    prep_x<<<8 * 16 * 64, 256>>>(x);

    dim3 grid(16, 4, 8), blk(256);

    if (g_streams_ok) {
        cudaEventRecord(g_fork, 0);
        cudaStreamWaitEvent(g_s1, g_fork, 0);
        for (int t = 0; t < 16; t++) {
            conv_x_half<<<grid, blk, SMEM_BYTES, g_s1>>>(t);
            cudaEventRecord(g_ea[t], g_s1);
        }
        for (int t = 0; t < 16; t++) {
            cudaStreamWaitEvent(0, g_ea[t], 0);
            conv_h_half<<<grid, blk, SMEM_BYTES>>>(hid, cell, t, t == 15 ? 1 : 0);
        }
    } else {
        for (int t = 0; t < 16; t++) {
            conv_x_half<<<grid, blk, SMEM_BYTES>>>(t);
            conv_h_half<<<grid, blk, SMEM_BYTES>>>(hid, cell, t, t == 15 ? 1 : 0);
        }
    }
}

// round 15
// speedup vs baseline: 2.0497x; 1.4014x over previous
#include <cuda_runtime.h>
#include <cuda_fp16.h>
#include <math.h>

// ConvLSTM, mma.sync m16n8k16 PURE fp16 (single term), step-split A/B.
// x, h, W all fp16; D = fp16(A) * fp16(W), fp32 accum. Measured error
// model (R14: 2.9e-4 with W 2-term) predicts ~4e-4 here — under 1e-3.
// A(t)=conv_x on low-priority stream -> partial; B(t)=conv_h+LSTM chain.
// CTA = 256 px (4 rows x 64) x 64 oc, 8 warps, 2 m-tiles/warp, 2 CTAs/SM.
// x: (8,16,64,64,64) f32, Wk: (256,128,3,3) f32
// out: [hid | cell], each 8*64*64*64 f32 (NCHW).

#define HW 64

__device__ __half g_xs[8][16][HW][HW][64];     // x channel-last fp16
__device__ __half g_hs[2][8][HW][HW][64];      // [parity] h fp16
__device__ __half g_wpk[4][8][9728];           // packed weights (hcg,kb): [ocl][152]
__device__ __align__(16) __half g_zero16[8] = {};
__device__ float4 g_part[16][2097152];         // per-step conv_x partial

// smem (fp16 elems): in buf = [k8half2][pix 396][8] = 6336 (x2 buffers)
//                    w  buf = [ocl 64][152]         = 9728
#define SIN_HALF_E  3168
#define SIN_BUF_E   6336
#define SMEM_BYTES  ((2 * 6336 + 9728) * 2)   // 44800 B

// ---------------- prep kernels ----------------

__global__ void prep_x(const float* __restrict__ x)
{
    __shared__ float tile[64][65];
    int y  = blockIdx.x & 63;
    int bt = blockIdx.x >> 6;               // b*16 + t
    const float* src = x + (size_t)bt * 64 * 4096 + y * 64;
    for (int i = threadIdx.x; i < 64 * 64; i += 256) {
        int ic = i >> 6, xx = i & 63;
        tile[ic][xx] = src[ic * 4096 + xx];
    }
    __syncthreads();
    int b = bt >> 4, t = bt & 15;
    for (int i = threadIdx.x; i < 64 * 64; i += 256) {
        int xx = i >> 6, ic = i & 63;
        g_xs[b][t][y][xx][ic] = __float2half(tile[ic][xx]);
    }
}

// Pack weights for (hcg,kb): [ocl 64][k 152], k = tap*16+ic (144 valid).
__global__ void prep_wpk(const float* __restrict__ Wk)
{
    int i = blockIdx.x * blockDim.x + threadIdx.x;  // over 4*8*9728
    if (i >= 4 * 8 * 9728) return;
    int e   = i % 9728;
    int kb  = (i / 9728) & 7;
    int hcg = i / (9728 * 8);
    int ocl = e / 152;
    int kk  = e - ocl * 152;
    __half out = __float2half(0.f);
    if (kk < 144) {
        int tap = kk >> 4, ic = kk & 15;
        int oc  = (ocl >> 4) * 64 + hcg * 16 + (ocl & 15);
        int cin = kb * 16 + ic;
        out = __float2half(Wk[(size_t)(oc * 128 + cin) * 9 + tap]);
    }
    g_wpk[hcg][kb][e] = out;
}

// ---------------- helpers ----------------

__device__ __forceinline__ void ldsm4(unsigned &r0, unsigned &r1,
                                      unsigned &r2, unsigned &r3, unsigned a)
{
    asm volatile("ldmatrix.sync.aligned.m8n8.x4.shared.b16 {%0,%1,%2,%3}, [%4];"
                 : "=r"(r0), "=r"(r1), "=r"(r2), "=r"(r3) : "r"(a));
}

__device__ __forceinline__ void mma_f16(float* c, const unsigned* a, const unsigned* b)
{
    asm volatile("mma.sync.aligned.m16n8k16.row.col.f32.f16.f16.f32 "
                 "{%0,%1,%2,%3},{%4,%5,%6,%7},{%8,%9},{%0,%1,%2,%3};"
                 : "+f"(c[0]), "+f"(c[1]), "+f"(c[2]), "+f"(c[3])
                 : "r"(a[0]), "r"(a[1]), "r"(a[2]), "r"(a[3]),
                   "r"(b[0]), "r"(b[1]));
}

__device__ __forceinline__ void cpasync16(unsigned dst, const void* src)
{
    asm volatile("cp.async.cg.shared.global [%0], [%1], 16;"
                 :: "r"(dst), "l"(src) : "memory");
}

// Shared 4-kb mainloop. HSRC=0: g_xs (uses t); HSRC=1: g_hs[t&1].
template <int HSRC>
__device__ __forceinline__ void conv_half(
    float acc[2][8][4], int t, int y0, int hcg, int b, int tid,
    const unsigned sIn0, const unsigned sIn1, const unsigned sW,
    const unsigned* laneA, unsigned laneB)
{
    const int par_in = t & 1;
    const int wkbase = HSRC ? 4 : 0;

    auto load_input = [&](int kb, unsigned sIn) {
        for (int c = tid; c < 792; c += 256) {
            int hf  = c / 396;
            int pix = c - hf * 396;
            int sy  = pix / 66, sx = pix - sy * 66;
            int gy  = y0 - 1 + sy, gx = sx - 1;
            const void* src = g_zero16;
            if ((unsigned)gy < 64u && (unsigned)gx < 64u)
                src = HSRC
                    ? (const void*)&g_hs[par_in][b][gy][gx][kb * 16 + hf * 8]
                    : (const void*)&g_xs[b][t][gy][gx][kb * 16 + hf * 8];
            unsigned dst = sIn + (unsigned)(hf * 396 + pix) * 16u;
            cpasync16(dst, src);
        }
    };

    load_input(0, sIn0);
    asm volatile("cp.async.commit_group;" ::: "memory");

    for (int kb = 0; kb < 4; kb++) {
        if (kb > 0) __syncthreads();

        {   // stage weights(kb): contiguous packed block (1216 x 16B)
            const char* wsrc = (const char*)g_wpk[hcg][wkbase + kb];
            for (int i = tid; i < 1216; i += 256)
                cpasync16(sW + (unsigned)i * 16u, wsrc + (size_t)i * 16);
        }
        asm volatile("cp.async.commit_group;" ::: "memory");

        if (kb + 1 < 4) {
            load_input(kb + 1, (kb + 1) & 1 ? sIn1 : sIn0);
            asm volatile("cp.async.commit_group;" ::: "memory");
            asm volatile("cp.async.wait_group 1;" ::: "memory");
        } else {
            asm volatile("cp.async.wait_group 0;" ::: "memory");
        }
        __syncthreads();

        const unsigned sIn = (kb & 1) ? sIn1 : sIn0;

#pragma unroll 1
        for (int tap = 0; tap < 9; tap++) {
            const int dyp = tap / 3, dxp = tap - dyp * 3;
            const unsigned aoff = (unsigned)(dyp * 66 + dxp) * 16u;
            const unsigned woff = (unsigned)(tap * 16) * 2u;

            unsigned a[2][4];   // [mt][frag]
#pragma unroll
            for (int mt = 0; mt < 2; mt++)
                ldsm4(a[mt][0], a[mt][1], a[mt][2], a[mt][3],
                      sIn + aoff + laneA[mt]);

            unsigned bf[8][2];
            unsigned base = sW + woff + laneB;
#pragma unroll
            for (int j = 0; j < 4; j++)
                ldsm4(bf[2 * j][0], bf[2 * j][1],
                      bf[2 * j + 1][0], bf[2 * j + 1][1],
                      base + (unsigned)(16 * j * 152) * 2u);
#pragma unroll
            for (int nf = 0; nf < 8; nf++)
#pragma unroll
                for (int mt = 0; mt < 2; mt++)
                    mma_f16(acc[mt][nf], a[mt], bf[nf]);
        }
    }
}

__device__ __forceinline__ void lane_setup(int w, int lane,
                                           unsigned* laneA, unsigned& laneB)
{
    const int t4 = lane >> 3, r8 = lane & 7;
    const int prA = ((t4 & 1) << 3) + r8;
    const int k8A = t4 >> 1;
#pragma unroll
    for (int mt = 0; mt < 2; mt++) {
        const int p0  = w * 32 + mt * 16 + prA;   // 0..255
        const int pyA = p0 >> 6;                  // local row 0..3
        const int pxA = p0 & 63;
        laneA[mt] = (unsigned)(k8A * SIN_HALF_E + (pyA * 66 + pxA) * 8) * 2u;
    }
    const int hi8 = (t4 >= 2) ? 8 : 0;
    laneB = (unsigned)((hi8 + r8) * 152 + 8 * (t4 & 1)) * 2u;
}

// ---------------- kernel A: conv_x half -> partial ----------------

__global__ __launch_bounds__(256, 2)
void conv_x_half(int t)
{
    extern __shared__ __half smem[];
    const unsigned sIn0 = (unsigned)__cvta_generic_to_shared(smem);
    const unsigned sIn1 = sIn0 + SIN_BUF_E * 2;
    const unsigned sW   = sIn0 + 2 * SIN_BUF_E * 2;

    const int tid  = threadIdx.x;
    const int w    = tid >> 5;
    const int lane = tid & 31;
    const int y0   = blockIdx.x * 4;
    const int hcg  = blockIdx.y;
    const int b    = blockIdx.z;

    unsigned laneA[2], laneB;
    lane_setup(w, lane, laneA, laneB);

    float acc[2][8][4];
#pragma unroll
    for (int m = 0; m < 2; m++)
#pragma unroll
        for (int i = 0; i < 8; i++)
#pragma unroll
            for (int j = 0; j < 4; j++) acc[m][i][j] = 0.f;

    conv_half<0>(acc, t, y0, hcg, b, tid, sIn0, sIn1, sW, laneA, laneB);

    const int slot = ((int)blockIdx.x * 4 + hcg) * 8 + b;   // 0..511
    float4* dst = g_part[t];
#pragma unroll
    for (int m = 0; m < 2; m++)
#pragma unroll
        for (int i = 0; i < 8; i++) {
            float4 v;
            v.x = acc[m][i][0]; v.y = acc[m][i][1];
            v.z = acc[m][i][2]; v.w = acc[m][i][3];
            dst[((size_t)slot * 16 + (m * 8 + i)) * 256 + tid] = v;
        }
}

// ---------------- kernel B: conv_h half + LSTM epilogue ----------------

__global__ __launch_bounds__(256, 2)
void conv_h_half(float* __restrict__ hid_out, float* __restrict__ cell_io,
                 int t, int last)
{
    extern __shared__ __half smem[];
    const unsigned sIn0 = (unsigned)__cvta_generic_to_shared(smem);
    const unsigned sIn1 = sIn0 + SIN_BUF_E * 2;
    const unsigned sW   = sIn0 + 2 * SIN_BUF_E * 2;

    const int tid  = threadIdx.x;
    const int w    = tid >> 5;
    const int lane = tid & 31;
    const int y0   = blockIdx.x * 4;
    const int hcg  = blockIdx.y;
    const int b    = blockIdx.z;
    const int par_out = (t + 1) & 1;

    unsigned laneA[2], laneB;
    lane_setup(w, lane, laneA, laneB);

    const int slot = ((int)blockIdx.x * 4 + hcg) * 8 + b;
    const float4* srcp = g_part[t];
    float acc[2][8][4];
#pragma unroll
    for (int m = 0; m < 2; m++)
#pragma unroll
        for (int i = 0; i < 8; i++) {
            float4 v = srcp[((size_t)slot * 16 + (m * 8 + i)) * 256 + tid];
            acc[m][i][0] = v.x; acc[m][i][1] = v.y;
            acc[m][i][2] = v.z; acc[m][i][3] = v.w;
        }

    if (t > 0)
        conv_half<1>(acc, t, y0, hcg, b, tid, sIn0, sIn1, sW, laneA, laneB);

    // ---- fused LSTM epilogue ----
    const int c0    = (lane & 3) * 2;
    const int rbase = lane >> 2;
#pragma unroll
    for (int mt = 0; mt < 2; mt++) {
#pragma unroll
        for (int rr = 0; rr < 2; rr++) {
            const int pe = w * 32 + mt * 16 + rbase + 8 * rr;
            const int y  = y0 + (pe >> 6);
            const int x  = pe & 63;
#pragma unroll
            for (int q = 0; q < 4; q++) {
                const int hcl  = c0 + (q & 1) + ((q >> 1) << 3);
                const int off2 = (hcl >= 8) ? 1 : 0;
                const int cidx = (hcl & 7) - c0 + rr * 2;
                float vi = acc[mt][0 + off2][cidx];
                float vf = acc[mt][2 + off2][cidx];
                float vo = acc[mt][4 + off2][cidx];
                float vg = acc[mt][6 + off2][cidx];
                float iv = 1.f / (1.f + __expf(-vi));
                float fv = 1.f / (1.f + __expf(-vf));
                float ov = 1.f / (1.f + __expf(-vo));
                float gv = tanhf(vg);
                const int hc = hcg * 16 + hcl;
                const size_t addr = (((size_t)b * 64 + hc) * 64 + y) * 64 + x;
                float cold = (t == 0) ? 0.f : cell_io[addr];
                float cnew = fv * cold + iv * gv;
                cell_io[addr] = cnew;
                float hval = ov * tanhf(cnew);
                if (last)
                    hid_out[addr] = hval;
                else
                    g_hs[par_out][b][y][x][hc] = __float2half(hval);
            }
        }
    }
}

// ---------------- host: streams/events (created pre-main) ----------------

static cudaStream_t g_s1 = 0;
static cudaEvent_t  g_fork = 0, g_ea[16];
static bool g_streams_ok = false;

struct StreamInit {
    StreamInit() {
        int lo = 0, hi = 0;
        if (cudaDeviceGetStreamPriorityRange(&lo, &hi) != cudaSuccess) return;
        if (cudaStreamCreateWithPriority(&g_s1, cudaStreamNonBlocking, lo)
            != cudaSuccess) return;
        if (cudaEventCreateWithFlags(&g_fork, cudaEventDisableTiming)
            != cudaSuccess) return;
        for (int i = 0; i < 16; i++)
            if (cudaEventCreateWithFlags(&g_ea[i], cudaEventDisableTiming)
                != cudaSuccess) return;
        g_streams_ok = true;
    }
};
static StreamInit g_stream_init;

extern "C" void kernel_launch(void* const* d_in, const int* in_sizes, int n_in,
                              void* d_out, int out_size)
{
    const float* x  = (const float*)d_in[0];
    const float* Wk = (const float*)d_in[1];
    float* out  = (float*)d_out;
    float* hid  = out;
    float* cell = out + out_size / 2;

    static bool attr_done = false;
    if (!attr_done) {
        cudaFuncSetAttribute(conv_x_half,
                             cudaFuncAttributeMaxDynamicSharedMemorySize, SMEM_BYTES);
        cudaFuncSetAttribute(conv_h_half,
                             cudaFuncAttributeMaxDynamicSharedMemorySize, SMEM_BYTES);
        attr_done = true;
    }

    prep_wpk<<<(4 * 8 * 9728 + 255) / 256, 256>>>(Wk);
    prep_x<<<8 * 16 * 64, 256>>>(x);

    dim3 grid(16, 4, 8), blk(256);

    if (g_streams_ok) {
        cudaEventRecord(g_fork, 0);
        cudaStreamWaitEvent(g_s1, g_fork, 0);
        for (int t = 0; t < 16; t++) {
            conv_x_half<<<grid, blk, SMEM_BYTES, g_s1>>>(t);
            cudaEventRecord(g_ea[t], g_s1);
        }
        for (int t = 0; t < 16; t++) {
            cudaStreamWaitEvent(0, g_ea[t], 0);
            conv_h_half<<<grid, blk, SMEM_BYTES>>>(hid, cell, t, t == 15 ? 1 : 0);
        }
    } else {
        for (int t = 0; t < 16; t++) {
            conv_x_half<<<grid, blk, SMEM_BYTES>>>(t);
            conv_h_half<<<grid, blk, SMEM_BYTES>>>(hid, cell, t, t == 15 ? 1 : 0);
        }
    }
}

// round 16
// speedup vs baseline: 2.0863x; 1.0178x over previous
#include <cuda_runtime.h>
#include <cuda_fp16.h>
#include <math.h>

// ConvLSTM, mma.sync m16n8k16 pure fp16, step-split A/B kernels.
// Round 16: fully-hidden staging (input AND weights double-buffered,
// wait_group(1) always one full kb behind) + tap-loop software pipeline
// (full unroll, ping-pong A-fragment prefetch) to hide LDSM->MMA latency.
// CTA = 256 px (4 rows x 64) x 64 oc, 8 warps, 2 m-tiles/warp, 2 CTAs/SM.
// x: (8,16,64,64,64) f32, Wk: (256,128,3,3) f32
// out: [hid | cell], each 8*64*64*64 f32 (NCHW).

#define HW 64

__device__ __half g_xs[8][16][HW][HW][64];     // x channel-last fp16
__device__ __half g_hs[2][8][HW][HW][64];      // [parity] h fp16
__device__ __half g_wpk[4][8][9728];           // packed weights (hcg,kb): [ocl][152]
__device__ __align__(16) __half g_zero16[8] = {};
__device__ float4 g_part[16][2097152];         // per-step conv_x partial

// smem (fp16 elems): in buf = [k8half2][pix 396][8] = 6336  (x2)
//                    w  buf = [ocl 64][152]         = 9728  (x2)
#define SIN_HALF_E  3168
#define SIN_BUF_E   6336
#define W_BUF_E     9728
#define SMEM_BYTES  ((2 * 6336 + 2 * 9728) * 2)   // 64256 B -> 2 CTAs/SM

// ---------------- prep kernels ----------------

__global__ void prep_x(const float* __restrict__ x)
{
    __shared__ float tile[64][65];
    int y  = blockIdx.x & 63;
    int bt = blockIdx.x >> 6;               // b*16 + t
    const float* src = x + (size_t)bt * 64 * 4096 + y * 64;
    for (int i = threadIdx.x; i < 64 * 64; i += 256) {
        int ic = i >> 6, xx = i & 63;
        tile[ic][xx] = src[ic * 4096 + xx];
    }
    __syncthreads();
    int b = bt >> 4, t = bt & 15;
    for (int i = threadIdx.x; i < 64 * 64; i += 256) {
        int xx = i >> 6, ic = i & 63;
        g_xs[b][t][y][xx][ic] = __float2half(tile[ic][xx]);
    }
}

// Pack weights for (hcg,kb): [ocl 64][k 152], k = tap*16+ic (144 valid).
__global__ void prep_wpk(const float* __restrict__ Wk)
{
    int i = blockIdx.x * blockDim.x + threadIdx.x;  // over 4*8*9728
    if (i >= 4 * 8 * 9728) return;
    int e   = i % 9728;
    int kb  = (i / 9728) & 7;
    int hcg = i / (9728 * 8);
    int ocl = e / 152;
    int kk  = e - ocl * 152;
    __half out = __float2half(0.f);
    if (kk < 144) {
        int tap = kk >> 4, ic = kk & 15;
        int oc  = (ocl >> 4) * 64 + hcg * 16 + (ocl & 15);
        int cin = kb * 16 + ic;
        out = __float2half(Wk[(size_t)(oc * 128 + cin) * 9 + tap]);
    }
    g_wpk[hcg][kb][e] = out;
}

// ---------------- helpers ----------------

__device__ __forceinline__ void ldsm4(unsigned &r0, unsigned &r1,
                                      unsigned &r2, unsigned &r3, unsigned a)
{
    asm volatile("ldmatrix.sync.aligned.m8n8.x4.shared.b16 {%0,%1,%2,%3}, [%4];"
                 : "=r"(r0), "=r"(r1), "=r"(r2), "=r"(r3) : "r"(a));
}

__device__ __forceinline__ void mma_f16(float* c, const unsigned* a, const unsigned* b)
{
    asm volatile("mma.sync.aligned.m16n8k16.row.col.f32.f16.f16.f32 "
                 "{%0,%1,%2,%3},{%4,%5,%6,%7},{%8,%9},{%0,%1,%2,%3};"
                 : "+f"(c[0]), "+f"(c[1]), "+f"(c[2]), "+f"(c[3])
                 : "r"(a[0]), "r"(a[1]), "r"(a[2]), "r"(a[3]),
                   "r"(b[0]), "r"(b[1]));
}

__device__ __forceinline__ void cpasync16(unsigned dst, const void* src)
{
    asm volatile("cp.async.cg.shared.global [%0], [%1], 16;"
                 :: "r"(dst), "l"(src) : "memory");
}

// Shared 4-kb mainloop. HSRC=0: g_xs (uses t); HSRC=1: g_hs[t&1].
// Input AND weights double-buffered; stage(kb+1) issued while stage(kb)
// (committed one full iteration earlier) is consumed -> wait is free.
template <int HSRC>
__device__ __forceinline__ void conv_half(
    float acc[2][8][4], int t, int y0, int hcg, int b, int tid,
    const unsigned sIn0, const unsigned sIn1,
    const unsigned sW0, const unsigned sW1,
    const unsigned* laneA, unsigned laneB)
{
    const int par_in = t & 1;
    const int wkbase = HSRC ? 4 : 0;

    auto load_stage = [&](int kb) {
        const unsigned sIn = (kb & 1) ? sIn1 : sIn0;
        const unsigned sW  = (kb & 1) ? sW1  : sW0;
        for (int c = tid; c < 792; c += 256) {
            int hf  = c / 396;
            int pix = c - hf * 396;
            int sy  = pix / 66, sx = pix - sy * 66;
            int gy  = y0 - 1 + sy, gx = sx - 1;
            const void* src = g_zero16;
            if ((unsigned)gy < 64u && (unsigned)gx < 64u)
                src = HSRC
                    ? (const void*)&g_hs[par_in][b][gy][gx][kb * 16 + hf * 8]
                    : (const void*)&g_xs[b][t][gy][gx][kb * 16 + hf * 8];
            cpasync16(sIn + (unsigned)(hf * 396 + pix) * 16u, src);
        }
        const char* wsrc = (const char*)g_wpk[hcg][wkbase + kb];
        for (int i = tid; i < 1216; i += 256)
            cpasync16(sW + (unsigned)i * 16u, wsrc + (size_t)i * 16);
    };

    load_stage(0);
    asm volatile("cp.async.commit_group;" ::: "memory");

    for (int kb = 0; kb < 4; kb++) {
        if (kb > 0) __syncthreads();   // buffers (kb-1)&1 free for reuse
        if (kb + 1 < 4) {
            load_stage(kb + 1);
            asm volatile("cp.async.commit_group;" ::: "memory");
            asm volatile("cp.async.wait_group 1;" ::: "memory");
        } else {
            asm volatile("cp.async.wait_group 0;" ::: "memory");
        }
        __syncthreads();

        const unsigned sIn = (kb & 1) ? sIn1 : sIn0;
        const unsigned sW  = (kb & 1) ? sW1  : sW0;

        // tap pipeline: A-frags for tap+1 load during tap's MMA block
        unsigned ap[2][2][4];   // [ping-pong][mt][frag]
#pragma unroll
        for (int mt = 0; mt < 2; mt++)
            ldsm4(ap[0][mt][0], ap[0][mt][1], ap[0][mt][2], ap[0][mt][3],
                  sIn + laneA[mt]);   // tap 0: aoff = 0

#pragma unroll
        for (int tap = 0; tap < 9; tap++) {
            const int cur = tap & 1, nxt = cur ^ 1;
            const unsigned woff = (unsigned)(tap * 16) * 2u;

            unsigned bf[8][2];
            unsigned base = sW + woff + laneB;
#pragma unroll
            for (int j = 0; j < 4; j++)
                ldsm4(bf[2 * j][0], bf[2 * j][1],
                      bf[2 * j + 1][0], bf[2 * j + 1][1],
                      base + (unsigned)(16 * j * 152) * 2u);

            if (tap < 8) {
                const int tn  = tap + 1;
                const int dyp = tn / 3, dxp = tn - dyp * 3;
                const unsigned aoff = (unsigned)(dyp * 66 + dxp) * 16u;
#pragma unroll
                for (int mt = 0; mt < 2; mt++)
                    ldsm4(ap[nxt][mt][0], ap[nxt][mt][1],
                          ap[nxt][mt][2], ap[nxt][mt][3],
                          sIn + aoff + laneA[mt]);
            }

#pragma unroll
            for (int nf = 0; nf < 8; nf++)
#pragma unroll
                for (int mt = 0; mt < 2; mt++)
                    mma_f16(acc[mt][nf], ap[cur][mt], bf[nf]);
        }
    }
}

__device__ __forceinline__ void lane_setup(int w, int lane,
                                           unsigned* laneA, unsigned& laneB)
{
    const int t4 = lane >> 3, r8 = lane & 7;
    const int prA = ((t4 & 1) << 3) + r8;
    const int k8A = t4 >> 1;
#pragma unroll
    for (int mt = 0; mt < 2; mt++) {
        const int p0  = w * 32 + mt * 16 + prA;   // 0..255
        const int pyA = p0 >> 6;                  // local row 0..3
        const int pxA = p0 & 63;
        laneA[mt] = (unsigned)(k8A * SIN_HALF_E + (pyA * 66 + pxA) * 8) * 2u;
    }
    const int hi8 = (t4 >= 2) ? 8 : 0;
    laneB = (unsigned)((hi8 + r8) * 152 + 8 * (t4 & 1)) * 2u;
}

// ---------------- kernel A: conv_x half -> partial ----------------

__global__ __launch_bounds__(256, 2)
void conv_x_half(int t)
{
    extern __shared__ __half smem[];
    const unsigned sIn0 = (unsigned)__cvta_generic_to_shared(smem);
    const unsigned sIn1 = sIn0 + SIN_BUF_E * 2;
    const unsigned sW0  = sIn0 + 2 * SIN_BUF_E * 2;
    const unsigned sW1  = sW0 + W_BUF_E * 2;

    const int tid  = threadIdx.x;
    const int w    = tid >> 5;
    const int lane = tid & 31;
    const int y0   = blockIdx.x * 4;
    const int hcg  = blockIdx.y;
    const int b    = blockIdx.z;

    unsigned laneA[2], laneB;
    lane_setup(w, lane, laneA, laneB);

    float acc[2][8][4];
#pragma unroll
    for (int m = 0; m < 2; m++)
#pragma unroll
        for (int i = 0; i < 8; i++)
#pragma unroll
            for (int j = 0; j < 4; j++) acc[m][i][j] = 0.f;

    conv_half<0>(acc, t, y0, hcg, b, tid, sIn0, sIn1, sW0, sW1, laneA, laneB);

    const int slot = ((int)blockIdx.x * 4 + hcg) * 8 + b;   // 0..511
    float4* dst = g_part[t];
#pragma unroll
    for (int m = 0; m < 2; m++)
#pragma unroll
        for (int i = 0; i < 8; i++) {
            float4 v;
            v.x = acc[m][i][0]; v.y = acc[m][i][1];
            v.z = acc[m][i][2]; v.w = acc[m][i][3];
            dst[((size_t)slot * 16 + (m * 8 + i)) * 256 + tid] = v;
        }
}

// ---------------- kernel B: conv_h half + LSTM epilogue ----------------

__global__ __launch_bounds__(256, 2)
void conv_h_half(float* __restrict__ hid_out, float* __restrict__ cell_io,
                 int t, int last)
{
    extern __shared__ __half smem[];
    const unsigned sIn0 = (unsigned)__cvta_generic_to_shared(smem);
    const unsigned sIn1 = sIn0 + SIN_BUF_E * 2;
    const unsigned sW0  = sIn0 + 2 * SIN_BUF_E * 2;
    const unsigned sW1  = sW0 + W_BUF_E * 2;

    const int tid  = threadIdx.x;
    const int w    = tid >> 5;
    const int lane = tid & 31;
    const int y0   = blockIdx.x * 4;
    const int hcg  = blockIdx.y;
    const int b    = blockIdx.z;
    const int par_out = (t + 1) & 1;

    unsigned laneA[2], laneB;
    lane_setup(w, lane, laneA, laneB);

    const int slot = ((int)blockIdx.x * 4 + hcg) * 8 + b;
    const float4* srcp = g_part[t];
    float acc[2][8][4];
#pragma unroll
    for (int m = 0; m < 2; m++)
#pragma unroll
        for (int i = 0; i < 8; i++) {
            float4 v = srcp[((size_t)slot * 16 + (m * 8 + i)) * 256 + tid];
            acc[m][i][0] = v.x; acc[m][i][1] = v.y;
            acc[m][i][2] = v.z; acc[m][i][3] = v.w;
        }

    if (t > 0)
        conv_half<1>(acc, t, y0, hcg, b, tid, sIn0, sIn1, sW0, sW1, laneA, laneB);

    // ---- fused LSTM epilogue ----
    const int c0    = (lane & 3) * 2;
    const int rbase = lane >> 2;
#pragma unroll
    for (int mt = 0; mt < 2; mt++) {
#pragma unroll
        for (int rr = 0; rr < 2; rr++) {
            const int pe = w * 32 + mt * 16 + rbase + 8 * rr;
            const int y  = y0 + (pe >> 6);
            const int x  = pe & 63;
#pragma unroll
            for (int q = 0; q < 4; q++) {
                const int hcl  = c0 + (q & 1) + ((q >> 1) << 3);
                const int off2 = (hcl >= 8) ? 1 : 0;
                const int cidx = (hcl & 7) - c0 + rr * 2;
                float vi = acc[mt][0 + off2][cidx];
                float vf = acc[mt][2 + off2][cidx];
                float vo = acc[mt][4 + off2][cidx];
                float vg = acc[mt][6 + off2][cidx];
                float iv = 1.f / (1.f + __expf(-vi));
                float fv = 1.f / (1.f + __expf(-vf));
                float ov = 1.f / (1.f + __expf(-vo));
                float gv = tanhf(vg);
                const int hc = hcg * 16 + hcl;
                const size_t addr = (((size_t)b * 64 + hc) * 64 + y) * 64 + x;
                float cold = (t == 0) ? 0.f : cell_io[addr];
                float cnew = fv * cold + iv * gv;
                cell_io[addr] = cnew;
                float hval = ov * tanhf(cnew);
                if (last)
                    hid_out[addr] = hval;
                else
                    g_hs[par_out][b][y][x][hc] = __float2half(hval);
            }
        }
    }
}

// ---------------- host: streams/events (created pre-main) ----------------

static cudaStream_t g_s1 = 0;
static cudaEvent_t  g_fork = 0, g_ea[16];
static bool g_streams_ok = false;

struct StreamInit {
    StreamInit() {
        int lo = 0, hi = 0;
        if (cudaDeviceGetStreamPriorityRange(&lo, &hi) != cudaSuccess) return;
        if (cudaStreamCreateWithPriority(&g_s1, cudaStreamNonBlocking, lo)
            != cudaSuccess) return;
        if (cudaEventCreateWithFlags(&g_fork, cudaEventDisableTiming)
            != cudaSuccess) return;
        for (int i = 0; i < 16; i++)
            if (cudaEventCreateWithFlags(&g_ea[i], cudaEventDisableTiming)
                != cudaSuccess) return;
        g_streams_ok = true;
    }
};
static StreamInit g_stream_init;

extern "C" void kernel_launch(void* const* d_in, const int* in_sizes, int n_in,
                              void* d_out, int out_size)
{
    const float* x  = (const float*)d_in[0];
    const float* Wk = (const float*)d_in[1];
    float* out  = (float*)d_out;
    float* hid  = out;
    float* cell = out + out_size / 2;

    static bool attr_done = false;
    if (!attr_done) {
        cudaFuncSetAttribute(conv_x_half,
                             cudaFuncAttributeMaxDynamicSharedMemorySize, SMEM_BYTES);
        cudaFuncSetAttribute(conv_h_half,
                             cudaFuncAttributeMaxDynamicSharedMemorySize, SMEM_BYTES);
        attr_done = true;
    }

    prep_wpk<<<(4 * 8 * 9728 + 255) / 256, 256>>>(Wk);
    prep_x<<<8 * 16 * 64, 256>>>(x);

    dim3 grid(16, 4, 8), blk(256);

    if (g_streams_ok) {
        cudaEventRecord(g_fork, 0);
        cudaStreamWaitEvent(g_s1, g_fork, 0);
        for (int t = 0; t < 16; t++) {
            conv_x_half<<<grid, blk, SMEM_BYTES, g_s1>>>(t);
            cudaEventRecord(g_ea[t], g_s1);
        }
        for (int t = 0; t < 16; t++) {
            cudaStreamWaitEvent(0, g_ea[t], 0);
            conv_h_half<<<grid, blk, SMEM_BYTES>>>(hid, cell, t, t == 15 ? 1 : 0);
        }
    } else {
        for (int t = 0; t < 16; t++) {
            conv_x_half<<<grid, blk, SMEM_BYTES>>>(t);
            conv_h_half<<<grid, blk, SMEM_BYTES>>>(hid, cell, t, t == 15 ? 1 : 0);
        }
    }
}

// round 17
// speedup vs baseline: 2.1225x; 1.0174x over previous
#include <cuda_runtime.h>
#include <cuda_fp16.h>
#include <math.h>

// ConvLSTM, mma.sync m16n8k16 pure fp16, step-split A/B kernels.
// Round 17: SINGLE-WAVE grids. CTA = 256 px (4 rows x 64) x TWO hcg groups
// processed sequentially; input tiles (all 4 kb) staged once and kept
// resident for both hcg; weights double-buffered across the 8 (hcg,kb)
// blocks. grid = 16 x 2 x 8 = 256 CTAs <= 296 resident slots -> no tail.
// x: (8,16,64,64,64) f32, Wk: (256,128,3,3) f32
// out: [hid | cell], each 8*64*64*64 f32 (NCHW).

#define HW 64

__device__ __half g_xs[8][16][HW][HW][64];     // x channel-last fp16
__device__ __half g_hs[2][8][HW][HW][64];      // [parity] h fp16
__device__ __half g_wpk[4][8][9728];           // packed weights (hcg,kb): [ocl][152]
__device__ __align__(16) __half g_zero16[8] = {};
__device__ float4 g_part[16][2097152];         // per-step conv_x partial

// smem (fp16 elems): input [kb4][k8half2][pix396][8] = 4*6336 = 25344
//                    weights [ocl 64][152] = 9728  (x2 buffers)
#define SIN_HALF_E  3168
#define SIN_BUF_E   6336
#define W_BUF_E     9728
#define SMEM_BYTES  ((4 * 6336 + 2 * 9728) * 2)   // 89600 B -> 2 CTAs/SM

// ---------------- prep kernels ----------------

__global__ void prep_x(const float* __restrict__ x)
{
    __shared__ float tile[64][65];
    int y  = blockIdx.x & 63;
    int bt = blockIdx.x >> 6;               // b*16 + t
    const float* src = x + (size_t)bt * 64 * 4096 + y * 64;
    for (int i = threadIdx.x; i < 64 * 64; i += 256) {
        int ic = i >> 6, xx = i & 63;
        tile[ic][xx] = src[ic * 4096 + xx];
    }
    __syncthreads();
    int b = bt >> 4, t = bt & 15;
    for (int i = threadIdx.x; i < 64 * 64; i += 256) {
        int xx = i >> 6, ic = i & 63;
        g_xs[b][t][y][xx][ic] = __float2half(tile[ic][xx]);
    }
}

// Pack weights for (hcg,kb): [ocl 64][k 152], k = tap*16+ic (144 valid).
__global__ void prep_wpk(const float* __restrict__ Wk)
{
    int i = blockIdx.x * blockDim.x + threadIdx.x;  // over 4*8*9728
    if (i >= 4 * 8 * 9728) return;
    int e   = i % 9728;
    int kb  = (i / 9728) & 7;
    int hcg = i / (9728 * 8);
    int ocl = e / 152;
    int kk  = e - ocl * 152;
    __half out = __float2half(0.f);
    if (kk < 144) {
        int tap = kk >> 4, ic = kk & 15;
        int oc  = (ocl >> 4) * 64 + hcg * 16 + (ocl & 15);
        int cin = kb * 16 + ic;
        out = __float2half(Wk[(size_t)(oc * 128 + cin) * 9 + tap]);
    }
    g_wpk[hcg][kb][e] = out;
}

// ---------------- helpers ----------------

__device__ __forceinline__ void ldsm4(unsigned &r0, unsigned &r1,
                                      unsigned &r2, unsigned &r3, unsigned a)
{
    asm volatile("ldmatrix.sync.aligned.m8n8.x4.shared.b16 {%0,%1,%2,%3}, [%4];"
                 : "=r"(r0), "=r"(r1), "=r"(r2), "=r"(r3) : "r"(a));
}

__device__ __forceinline__ void mma_f16(float* c, const unsigned* a, const unsigned* b)
{
    asm volatile("mma.sync.aligned.m16n8k16.row.col.f32.f16.f16.f32 "
                 "{%0,%1,%2,%3},{%4,%5,%6,%7},{%8,%9},{%0,%1,%2,%3};"
                 : "+f"(c[0]), "+f"(c[1]), "+f"(c[2]), "+f"(c[3])
                 : "r"(a[0]), "r"(a[1]), "r"(a[2]), "r"(a[3]),
                   "r"(b[0]), "r"(b[1]));
}

__device__ __forceinline__ void cpasync16(unsigned dst, const void* src)
{
    asm volatile("cp.async.cg.shared.global [%0], [%1], 16;"
                 :: "r"(dst), "l"(src) : "memory");
}

__device__ __forceinline__ void lane_setup(int w, int lane,
                                           unsigned* laneA, unsigned& laneB)
{
    const int t4 = lane >> 3, r8 = lane & 7;
    const int prA = ((t4 & 1) << 3) + r8;
    const int k8A = t4 >> 1;
#pragma unroll
    for (int mt = 0; mt < 2; mt++) {
        const int p0  = w * 32 + mt * 16 + prA;   // 0..255
        const int pyA = p0 >> 6;                  // local row 0..3
        const int pxA = p0 & 63;
        laneA[mt] = (unsigned)(k8A * SIN_HALF_E + (pyA * 66 + pxA) * 8) * 2u;
    }
    const int hi8 = (t4 >= 2) ? 8 : 0;
    laneB = (unsigned)((hi8 + r8) * 152 + 8 * (t4 & 1)) * 2u;
}

// ---------------- main body (shared by A and B kernels) ----------------
// HSRC=0: conv_x (init acc = 0, finalize -> g_part)
// HSRC=1: conv_h (init acc = g_part, finalize -> LSTM epilogue)

template <int HSRC>
__device__ __forceinline__ void run_two_hcg(
    float* hid_out, float* cell_io, int t, int last)
{
    extern __shared__ __half smem[];
    const unsigned sInB = (unsigned)__cvta_generic_to_shared(smem);
    const unsigned sW0  = sInB + 4 * SIN_BUF_E * 2;
    const unsigned sW1  = sW0 + W_BUF_E * 2;

    const int tid  = threadIdx.x;
    const int w    = tid >> 5;
    const int lane = tid & 31;
    const int y0   = blockIdx.x * 4;
    const int hcg0 = blockIdx.y * 2;      // first of the pair
    const int b    = blockIdx.z;
    const int par_in  = t & 1;
    const int par_out = (t + 1) & 1;
    const int wkbase  = HSRC ? 4 : 0;

    unsigned laneA[2], laneB;
    lane_setup(w, lane, laneA, laneB);

    const int c0    = (lane & 3) * 2;
    const int rbase = lane >> 2;

    // ---- stage ALL 4 input kb tiles + weights(s=0), one commit group ----
    if (!(HSRC && t == 0)) {
        for (int kb = 0; kb < 4; kb++) {
            const unsigned sIn = sInB + (unsigned)kb * SIN_BUF_E * 2u;
            for (int c = tid; c < 792; c += 256) {
                int hf  = c / 396;
                int pix = c - hf * 396;
                int sy  = pix / 66, sx = pix - sy * 66;
                int gy  = y0 - 1 + sy, gx = sx - 1;
                const void* src = g_zero16;
                if ((unsigned)gy < 64u && (unsigned)gx < 64u)
                    src = HSRC
                        ? (const void*)&g_hs[par_in][b][gy][gx][kb * 16 + hf * 8]
                        : (const void*)&g_xs[b][t][gy][gx][kb * 16 + hf * 8];
                cpasync16(sIn + (unsigned)(hf * 396 + pix) * 16u, src);
            }
        }
        {
            const char* wsrc = (const char*)g_wpk[hcg0][wkbase];
            for (int i = tid; i < 1216; i += 256)
                cpasync16(sW0 + (unsigned)i * 16u, wsrc + (size_t)i * 16);
        }
        asm volatile("cp.async.commit_group;" ::: "memory");
    }

    float acc[2][8][4];

#pragma unroll 1
    for (int i = 0; i < 2; i++) {
        const int hcg  = hcg0 + i;
        const int slot = ((int)blockIdx.x * 4 + hcg) * 8 + b;

        // acc init
        if (HSRC) {
            const float4* srcp = g_part[t];
#pragma unroll
            for (int m = 0; m < 2; m++)
#pragma unroll
                for (int q = 0; q < 8; q++) {
                    float4 v = srcp[((size_t)slot * 16 + (m * 8 + q)) * 256 + tid];
                    acc[m][q][0] = v.x; acc[m][q][1] = v.y;
                    acc[m][q][2] = v.z; acc[m][q][3] = v.w;
                }
        } else {
#pragma unroll
            for (int m = 0; m < 2; m++)
#pragma unroll
                for (int q = 0; q < 8; q++)
#pragma unroll
                    for (int j = 0; j < 4; j++) acc[m][q][j] = 0.f;
        }

        if (!(HSRC && t == 0)) {
#pragma unroll 1
            for (int kb = 0; kb < 4; kb++) {
                const int s = i * 4 + kb;
                if (s > 0) __syncthreads();   // buf (s+1)&1 reads (iter s-1) done
                if (s + 1 < 8) {
                    const int sn  = s + 1;
                    const int hn  = hcg0 + (sn >> 2);
                    const char* wsrc = (const char*)g_wpk[hn][wkbase + (sn & 3)];
                    const unsigned sWn = (sn & 1) ? sW1 : sW0;
                    for (int c = tid; c < 1216; c += 256)
                        cpasync16(sWn + (unsigned)c * 16u, wsrc + (size_t)c * 16);
                    asm volatile("cp.async.commit_group;" ::: "memory");
                    asm volatile("cp.async.wait_group 1;" ::: "memory");
                } else {
                    asm volatile("cp.async.wait_group 0;" ::: "memory");
                }
                __syncthreads();

                const unsigned sIn = sInB + (unsigned)kb * SIN_BUF_E * 2u;
                const unsigned sW  = (s & 1) ? sW1 : sW0;

#pragma unroll 1
                for (int tap = 0; tap < 9; tap++) {
                    const int dyp = tap / 3, dxp = tap - dyp * 3;
                    const unsigned aoff = (unsigned)(dyp * 66 + dxp) * 16u;
                    const unsigned woff = (unsigned)(tap * 16) * 2u;

                    unsigned a[2][4];
#pragma unroll
                    for (int mt = 0; mt < 2; mt++)
                        ldsm4(a[mt][0], a[mt][1], a[mt][2], a[mt][3],
                              sIn + aoff + laneA[mt]);

                    unsigned bf[8][2];
                    unsigned base = sW + woff + laneB;
#pragma unroll
                    for (int j = 0; j < 4; j++)
                        ldsm4(bf[2 * j][0], bf[2 * j][1],
                              bf[2 * j + 1][0], bf[2 * j + 1][1],
                              base + (unsigned)(16 * j * 152) * 2u);
#pragma unroll
                    for (int nf = 0; nf < 8; nf++)
#pragma unroll
                        for (int mt = 0; mt < 2; mt++)
                            mma_f16(acc[mt][nf], a[mt], bf[nf]);
                }
            }
        }

        // finalize
        if (!HSRC) {
            float4* dst = g_part[t];
#pragma unroll
            for (int m = 0; m < 2; m++)
#pragma unroll
                for (int q = 0; q < 8; q++) {
                    float4 v;
                    v.x = acc[m][q][0]; v.y = acc[m][q][1];
                    v.z = acc[m][q][2]; v.w = acc[m][q][3];
                    dst[((size_t)slot * 16 + (m * 8 + q)) * 256 + tid] = v;
                }
        } else {
#pragma unroll
            for (int mt = 0; mt < 2; mt++) {
#pragma unroll
                for (int rr = 0; rr < 2; rr++) {
                    const int pe = w * 32 + mt * 16 + rbase + 8 * rr;
                    const int y  = y0 + (pe >> 6);
                    const int x  = pe & 63;
#pragma unroll
                    for (int q = 0; q < 4; q++) {
                        const int hcl  = c0 + (q & 1) + ((q >> 1) << 3);
                        const int off2 = (hcl >= 8) ? 1 : 0;
                        const int cidx = (hcl & 7) - c0 + rr * 2;
                        float vi = acc[mt][0 + off2][cidx];
                        float vf = acc[mt][2 + off2][cidx];
                        float vo = acc[mt][4 + off2][cidx];
                        float vg = acc[mt][6 + off2][cidx];
                        float iv = 1.f / (1.f + __expf(-vi));
                        float fv = 1.f / (1.f + __expf(-vf));
                        float ov = 1.f / (1.f + __expf(-vo));
                        float gv = tanhf(vg);
                        const int hc = hcg * 16 + hcl;
                        const size_t addr =
                            (((size_t)b * 64 + hc) * 64 + y) * 64 + x;
                        float cold = (t == 0) ? 0.f : cell_io[addr];
                        float cnew = fv * cold + iv * gv;
                        cell_io[addr] = cnew;
                        float hval = ov * tanhf(cnew);
                        if (last)
                            hid_out[addr] = hval;
                        else
                            g_hs[par_out][b][y][x][hc] = __float2half(hval);
                    }
                }
            }
        }
    }
}

__global__ __launch_bounds__(256, 2)
void conv_x_half(int t)
{
    run_two_hcg<0>(nullptr, nullptr, t, 0);
}

__global__ __launch_bounds__(256, 2)
void conv_h_half(float* __restrict__ hid_out, float* __restrict__ cell_io,
                 int t, int last)
{
    run_two_hcg<1>(hid_out, cell_io, t, last);
}

// ---------------- host: streams/events (created pre-main) ----------------

static cudaStream_t g_s1 = 0;
static cudaEvent_t  g_fork = 0, g_ea[16];
static bool g_streams_ok = false;

struct StreamInit {
    StreamInit() {
        int lo = 0, hi = 0;
        if (cudaDeviceGetStreamPriorityRange(&lo, &hi) != cudaSuccess) return;
        if (cudaStreamCreateWithPriority(&g_s1, cudaStreamNonBlocking, lo)
            != cudaSuccess) return;
        if (cudaEventCreateWithFlags(&g_fork, cudaEventDisableTiming)
            != cudaSuccess) return;
        for (int i = 0; i < 16; i++)
            if (cudaEventCreateWithFlags(&g_ea[i], cudaEventDisableTiming)
                != cudaSuccess) return;
        g_streams_ok = true;
    }
};
static StreamInit g_stream_init;

extern "C" void kernel_launch(void* const* d_in, const int* in_sizes, int n_in,
                              void* d_out, int out_size)
{
    const float* x  = (const float*)d_in[0];
    const float* Wk = (const float*)d_in[1];
    float* out  = (float*)d_out;
    float* hid  = out;
    float* cell = out + out_size / 2;

    static bool attr_done = false;
    if (!attr_done) {
        cudaFuncSetAttribute(conv_x_half,
                             cudaFuncAttributeMaxDynamicSharedMemorySize, SMEM_BYTES);
        cudaFuncSetAttribute(conv_h_half,
                             cudaFuncAttributeMaxDynamicSharedMemorySize, SMEM_BYTES);
        attr_done = true;
    }

    prep_wpk<<<(4 * 8 * 9728 + 255) / 256, 256>>>(Wk);
    prep_x<<<8 * 16 * 64, 256>>>(x);

    dim3 grid(16, 2, 8), blk(256);   // 256 CTAs -> single wave

    if (g_streams_ok) {
        cudaEventRecord(g_fork, 0);
        cudaStreamWaitEvent(g_s1, g_fork, 0);
        for (int t = 0; t < 16; t++) {
            conv_x_half<<<grid, blk, SMEM_BYTES, g_s1>>>(t);
            cudaEventRecord(g_ea[t], g_s1);
        }
        for (int t = 0; t < 16; t++) {
            cudaStreamWaitEvent(0, g_ea[t], 0);
            conv_h_half<<<grid, blk, SMEM_BYTES>>>(hid, cell, t, t == 15 ? 1 : 0);
        }
    } else {
        for (int t = 0; t < 16; t++) {
            conv_x_half<<<grid, blk, SMEM_BYTES>>>(t);
            conv_h_half<<<grid, blk, SMEM_BYTES>>>(hid, cell, t, t == 15 ? 1 : 0);
        }
    }
}